// round 9
// baseline (speedup 1.0000x reference)
#include <cuda_runtime.h>
#include <cstdint>

#define BB 32
#define SS 2048
#define HH 1024
#define D2H 2048

// Scratch (device globals — no allocation allowed)
__device__ float g_wq[BB * HH];          // W(dh) + W_b + U_b
__device__ float g_scores[BB * SS];
__device__ float g_weights[BB * SS];
__device__ float g_part[8 * BB * D2H];

// ---------------------------------------------------------------------------
// score_kernel tiling: CTA = 128 rows (one b, one s-tile) x N looped in 8
// chunks of 128. mma.sync.m16n8k8 tf32, 8 warps as 4(M) x 2(N), warp 32x64.
// 2-stage cp.async pipeline on the K dimension (chunks of 32 floats = 128B).
// ---------------------------------------------------------------------------
#define LDA 36                    // smem row stride (floats), conflict-free
#define STG (128 * LDA)           // floats per matrix tile (A or B) per stage
#define STAGE (2 * STG)           // A + B per stage
#define DYN_BYTES (2 * STAGE * 4) // 2 stages = 73728 B

__device__ __forceinline__ uint32_t s2u(const void* p) {
    uint32_t a;
    asm("{ .reg .u64 t; cvta.to.shared.u64 t, %1; cvt.u32.u64 %0, t; }"
        : "=r"(a) : "l"(p));
    return a;
}
__device__ __forceinline__ void cp16(uint32_t dst, const void* src) {
    asm volatile("cp.async.cg.shared.global [%0], [%1], 16;"
                 :: "r"(dst), "l"(src) : "memory");
}

// ---------------------------------------------------------------------------
// Kernel A: wq[b][k] = dh[b]·W_w[k] + W_b[k] + U_b[k]
// ---------------------------------------------------------------------------
__global__ void wq_kernel(const float* __restrict__ dh,
                          const float* __restrict__ W_w,
                          const float* __restrict__ W_b,
                          const float* __restrict__ U_b) {
    int b = blockIdx.x;
    int k = blockIdx.y * 128 + threadIdx.x;
    __shared__ float dh_s[HH];
    for (int i = threadIdx.x; i < HH; i += 128) dh_s[i] = dh[b * HH + i];
    __syncthreads();
    const float4* wrow = reinterpret_cast<const float4*>(W_w + (size_t)k * HH);
    const float4* dv   = reinterpret_cast<const float4*>(dh_s);
    float acc = 0.f;
#pragma unroll 8
    for (int i = 0; i < HH / 4; i++) {
        float4 w = wrow[i];
        float4 d = dv[i];
        acc += w.x * d.x + w.y * d.y + w.z * d.z + w.w * d.w;
    }
    g_wq[b * HH + k] = acc + W_b[k] + U_b[k];
}

// ---------------------------------------------------------------------------
// Kernel B: fused GEMM(enc @ U^T) + tanh + V-dot -> scores[b][s]
// ---------------------------------------------------------------------------
__global__ __launch_bounds__(256, 2)
void score_kernel(const float* __restrict__ enc,
                  const float* __restrict__ Uw,
                  const float* __restrict__ Vw) {
    extern __shared__ float dyn[];          // 2 stages x (A tile + B tile)
    __shared__ float wq_all[HH];
    __shared__ float V_all[HH];
    __shared__ float scores_s[128];

    const int tid  = threadIdx.x;
    const int lane = tid & 31;
    const int warp = tid >> 5;
    const int wm   = warp & 3;    // warp row (0..3) -> 32 rows
    const int wn   = warp >> 2;   // warp col (0..1) -> 64 cols
    const int gid  = lane >> 2;
    const int tig  = lane & 3;

    const int b     = blockIdx.x >> 4;
    const int stile = blockIdx.x & 15;

    for (int i = tid; i < HH; i += 256) {
        wq_all[i] = g_wq[b * HH + i];
        V_all[i]  = Vw[i];
    }
    if (tid < 128) scores_s[tid] = 0.f;

    // cp.async per-thread coords: thread covers rows r0+{0,32,64,96}, 16B seg sg
    const uint32_t dbase = s2u(dyn);
    const int r0 = tid >> 3;                          // 0..31
    const int sg = tid & 7;
    const uint32_t doff = (uint32_t)((r0 * LDA + sg * 4) * 4);  // 16B aligned
    const float* Abase = enc + ((size_t)(b * SS + stile * 128) + r0) * D2H + sg * 4;

    float sp[2][2] = {{0.f, 0.f}, {0.f, 0.f}};
    __syncthreads();

    for (int nc = 0; nc < 8; nc++) {
        const float* Bbase = Uw + ((size_t)(nc * 128) + r0) * D2H + sg * 4;

        float acc[2][8][4];
#pragma unroll
        for (int mt = 0; mt < 2; mt++)
#pragma unroll
            for (int nt = 0; nt < 8; nt++)
#pragma unroll
                for (int j = 0; j < 4; j++) acc[mt][nt][j] = 0.f;

        // Prologue: stage 0 <- chunk 0
        {
            const uint32_t dA = dbase + doff;
            const uint32_t dB = dA + STG * 4;
#pragma unroll
            for (int i = 0; i < 4; i++) {
                cp16(dA + i * (32 * LDA * 4), Abase + (size_t)i * 32 * D2H);
                cp16(dB + i * (32 * LDA * 4), Bbase + (size_t)i * 32 * D2H);
            }
            asm volatile("cp.async.commit_group;" ::: "memory");
        }

        for (int kc = 0; kc < 64; kc++) {
            if (kc < 63) {
                // Issue next chunk into the other stage (safe: that stage's
                // readers finished at iter kc-1's trailing barrier).
                const uint32_t dA =
                    dbase + ((kc + 1) & 1) * (STAGE * 4) + doff;
                const uint32_t dB = dA + STG * 4;
                const float* a  = Abase + (kc + 1) * 32;
                const float* bb = Bbase + (kc + 1) * 32;
#pragma unroll
                for (int i = 0; i < 4; i++) {
                    cp16(dA + i * (32 * LDA * 4), a + (size_t)i * 32 * D2H);
                    cp16(dB + i * (32 * LDA * 4), bb + (size_t)i * 32 * D2H);
                }
                asm volatile("cp.async.commit_group;" ::: "memory");
                asm volatile("cp.async.wait_group 1;" ::: "memory");
            } else {
                asm volatile("cp.async.wait_group 0;" ::: "memory");
            }
            __syncthreads();

            const float* As = dyn + (kc & 1) * STAGE;
            const uint32_t* Au = reinterpret_cast<const uint32_t*>(As);
            const uint32_t* Bu = reinterpret_cast<const uint32_t*>(As + STG);
#pragma unroll
            for (int kk = 0; kk < 4; kk++) {
                const int k0 = kk * 8;
                uint32_t af[2][4];
#pragma unroll
                for (int mt = 0; mt < 2; mt++) {
                    int rf = (wm * 32 + mt * 16 + gid) * LDA + k0 + tig;
                    af[mt][0] = Au[rf];
                    af[mt][1] = Au[rf + 8 * LDA];
                    af[mt][2] = Au[rf + 4];
                    af[mt][3] = Au[rf + 8 * LDA + 4];
                }
                uint32_t bf[8][2];
#pragma unroll
                for (int nt = 0; nt < 8; nt++) {
                    int c0 = (wn * 64 + nt * 8 + gid) * LDA + k0 + tig;
                    bf[nt][0] = Bu[c0];
                    bf[nt][1] = Bu[c0 + 4];
                }
#pragma unroll
                for (int mt = 0; mt < 2; mt++)
#pragma unroll
                    for (int nt = 0; nt < 8; nt++) {
                        asm volatile(
                            "mma.sync.aligned.m16n8k8.row.col.f32.tf32.tf32.f32 "
                            "{%0,%1,%2,%3}, {%4,%5,%6,%7}, {%8,%9}, {%0,%1,%2,%3};"
                            : "+f"(acc[mt][nt][0]), "+f"(acc[mt][nt][1]),
                              "+f"(acc[mt][nt][2]), "+f"(acc[mt][nt][3])
                            : "r"(af[mt][0]), "r"(af[mt][1]),
                              "r"(af[mt][2]), "r"(af[mt][3]),
                              "r"(bf[nt][0]), "r"(bf[nt][1]));
                    }
            }
            __syncthreads();   // protect stage reuse at iter kc+1's issue
        }

        // Epilogue: tanh(acc + wq) * V, accumulated per row
#pragma unroll
        for (int mt = 0; mt < 2; mt++)
#pragma unroll
            for (int nt = 0; nt < 8; nt++)
#pragma unroll
                for (int j = 0; j < 4; j++) {
                    const int nl = wn * 64 + nt * 8 + 2 * tig + (j & 1);
                    const float x = acc[mt][nt][j] + wq_all[nc * 128 + nl];
                    const float e = __expf(2.f * x);
                    sp[mt][j >> 1] += (1.f - 2.f / (e + 1.f)) * V_all[nc * 128 + nl];
                }
    }

    // Reduce partial scores: 4 lanes/group share a row; 2 N-warps share a row
#pragma unroll
    for (int mt = 0; mt < 2; mt++)
#pragma unroll
        for (int rh = 0; rh < 2; rh++) {
            float v = sp[mt][rh];
            v += __shfl_xor_sync(0xffffffffu, v, 1);
            v += __shfl_xor_sync(0xffffffffu, v, 2);
            if (tig == 0)
                atomicAdd(&scores_s[wm * 32 + mt * 16 + rh * 8 + gid], v);
        }
    __syncthreads();
    if (tid < 128)   // V_b omitted: softmax is shift-invariant
        g_scores[(size_t)b * SS + stile * 128 + tid] = scores_s[tid];
}

// ---------------------------------------------------------------------------
// Kernel C: softmax over S per batch
// ---------------------------------------------------------------------------
__global__ void softmax_kernel() {
    int b = blockIdx.x, tid = threadIdx.x;   // 256 threads
    __shared__ float red[256];
    float v[8];
    float mx = -1e30f;
#pragma unroll
    for (int i = 0; i < 8; i++) {
        v[i] = g_scores[b * SS + i * 256 + tid];
        mx = fmaxf(mx, v[i]);
    }
    red[tid] = mx;
    __syncthreads();
    for (int s = 128; s > 0; s >>= 1) {
        if (tid < s) red[tid] = fmaxf(red[tid], red[tid + s]);
        __syncthreads();
    }
    mx = red[0];
    __syncthreads();
    float sum = 0.f;
#pragma unroll
    for (int i = 0; i < 8; i++) {
        v[i] = __expf(v[i] - mx);
        sum += v[i];
    }
    red[tid] = sum;
    __syncthreads();
    for (int s = 128; s > 0; s >>= 1) {
        if (tid < s) red[tid] += red[tid + s];
        __syncthreads();
    }
    const float inv = 1.f / red[0];
#pragma unroll
    for (int i = 0; i < 8; i++)
        g_weights[b * SS + i * 256 + tid] = v[i] * inv;
}

// ---------------------------------------------------------------------------
// Kernel D1: partial context over an S-chunk (deterministic, no atomics)
// ---------------------------------------------------------------------------
__global__ void ctx_part_kernel(const float* __restrict__ enc) {
    int bb = blockIdx.x, sc = blockIdx.y, t = threadIdx.x;   // 512 threads
    __shared__ float w_s[256];
    if (t < 256) w_s[t] = g_weights[bb * SS + sc * 256 + t];
    __syncthreads();
    const float4* base =
        reinterpret_cast<const float4*>(enc + ((size_t)bb * SS + (size_t)sc * 256) * D2H);
    float4 acc = make_float4(0.f, 0.f, 0.f, 0.f);
#pragma unroll 4
    for (int s = 0; s < 256; s++) {
        float w = w_s[s];
        float4 e = base[(size_t)s * (D2H / 4) + t];
        acc.x += w * e.x; acc.y += w * e.y;
        acc.z += w * e.z; acc.w += w * e.w;
    }
    *reinterpret_cast<float4*>(g_part + ((size_t)sc * BB + bb) * D2H + t * 4) = acc;
}

// Kernel D2: sum the 8 S-chunk partials -> output [B, 1, 2H]
__global__ void ctx_reduce_kernel(float* __restrict__ out) {
    int i = blockIdx.x * blockDim.x + threadIdx.x;
    float s = 0.f;
#pragma unroll
    for (int sc = 0; sc < 8; sc++) s += g_part[sc * (BB * D2H) + i];
    out[i] = s;
}

// ---------------------------------------------------------------------------
extern "C" void kernel_launch(void* const* d_in, const int* in_sizes, int n_in,
                              void* d_out, int out_size) {
    const float* enc = (const float*)d_in[0];   // [32, 2048, 2048]
    const float* dh  = (const float*)d_in[1];   // [1, 32, 1024]
    const float* W_w = (const float*)d_in[2];   // [1024, 1024]
    const float* W_b = (const float*)d_in[3];   // [1024]
    const float* U_w = (const float*)d_in[4];   // [1024, 2048]
    const float* U_b = (const float*)d_in[5];   // [1024]
    const float* V_w = (const float*)d_in[6];   // [1, 1024]
    float* out = (float*)d_out;                 // [32, 1, 2048]

    cudaFuncSetAttribute(score_kernel,
                         cudaFuncAttributeMaxDynamicSharedMemorySize, DYN_BYTES);

    wq_kernel<<<dim3(32, 8), 128>>>(dh, W_w, W_b, U_b);
    score_kernel<<<512, 256, DYN_BYTES>>>(enc, U_w, V_w);
    softmax_kernel<<<32, 256>>>();
    ctx_part_kernel<<<dim3(32, 8), 512>>>(enc);
    ctx_reduce_kernel<<<128, 512>>>(out);
}

// round 10
// speedup vs baseline: 2.1701x; 2.1701x over previous
#include <cuda_runtime.h>
#include <cuda_fp16.h>
#include <cstdint>

#define BB 32
#define SS 2048
#define HH 1024
#define D2H 2048

// Scratch (device globals — no allocation allowed)
__device__ float g_wq[BB * HH];          // W(dh) + W_b + U_b
__device__ float g_scores[BB * SS];
__device__ float g_weights[BB * SS];
__device__ float g_part[8 * BB * D2H];

__device__ __forceinline__ uint32_t f2h2(float x, float y) {
    __half2 h = __floats2half2_rn(x, y);
    return *reinterpret_cast<uint32_t*>(&h);
}

// ---------------------------------------------------------------------------
// Kernel A: wq[b][k] = dh[b]·W_w[k] + W_b[k] + U_b[k]
// ---------------------------------------------------------------------------
__global__ void wq_kernel(const float* __restrict__ dh,
                          const float* __restrict__ W_w,
                          const float* __restrict__ W_b,
                          const float* __restrict__ U_b) {
    int b = blockIdx.x;
    int k = blockIdx.y * 128 + threadIdx.x;
    __shared__ float dh_s[HH];
    for (int i = threadIdx.x; i < HH; i += 128) dh_s[i] = dh[b * HH + i];
    __syncthreads();
    const float4* wrow = reinterpret_cast<const float4*>(W_w + (size_t)k * HH);
    const float4* dv   = reinterpret_cast<const float4*>(dh_s);
    float acc = 0.f;
#pragma unroll 8
    for (int i = 0; i < HH / 4; i++) {
        float4 w = wrow[i];
        float4 d = dv[i];
        acc += w.x * d.x + w.y * d.y + w.z * d.z + w.w * d.w;
    }
    g_wq[b * HH + k] = acc + W_b[k] + U_b[k];
}

// ---------------------------------------------------------------------------
// Kernel B: fused GEMM(enc @ U^T) + tanh + V-dot -> scores[b][s]
// CTA: 128 rows (one b, one s-tile) x N looped in 8 chunks of 128.
// fp16 mma.sync.m16n8k16, fp32 accum. 8 warps as 4(M) x 2(N), warp 32x64.
// K-chunk = 64 elements (128B/row as fp16), single-stage smem, 2 CTAs/SM.
// ---------------------------------------------------------------------------
#define LDW 36   // smem row stride in 32-bit words (32 half2 + 4 pad)

__global__ __launch_bounds__(256, 2)
void score_kernel(const float* __restrict__ enc,
                  const float* __restrict__ Uw,
                  const float* __restrict__ Vw) {
    __shared__ uint32_t A_s[128 * LDW];   // enc tile  [m][k] as half2 words
    __shared__ uint32_t B_s[128 * LDW];   // U_w tile  [n][k] as half2 words
    __shared__ float wq_s[128];
    __shared__ float V_s[128];
    __shared__ float scores_s[128];

    const int tid  = threadIdx.x;
    const int lane = tid & 31;
    const int warp = tid >> 5;
    const int wm   = warp & 3;    // warp row (0..3) -> 32 rows each
    const int wn   = warp >> 2;   // warp col (0..1) -> 64 cols each
    const int gid  = lane >> 2;   // group id (0..7)
    const int tig  = lane & 3;    // thread-in-group

    const int b     = blockIdx.x >> 4;
    const int stile = blockIdx.x & 15;

    // Loader coords: seg = 4-float segment (0..15), rows row0 + 16*i
    const int seg  = tid & 15;
    const int row0 = tid >> 4;    // 0..15
    const float* Abase =
        enc + ((size_t)(b * SS + stile * 128) + row0) * D2H + seg * 4;

    if (tid < 128) scores_s[tid] = 0.f;

    float sp[2][2] = {{0.f, 0.f}, {0.f, 0.f}};

    for (int nc = 0; nc < 8; nc++) {
        __syncthreads();   // epilogue of prev nc done: wq_s/V_s safe to rewrite
        if (tid < 128) {
            wq_s[tid] = g_wq[b * HH + nc * 128 + tid];
            V_s[tid]  = Vw[nc * 128 + tid];
        }
        const float* Bbase =
            Uw + ((size_t)(nc * 128) + row0) * D2H + seg * 4;

        float acc[2][8][4];
#pragma unroll
        for (int mt = 0; mt < 2; mt++)
#pragma unroll
            for (int nt = 0; nt < 8; nt++)
#pragma unroll
                for (int j = 0; j < 4; j++) acc[mt][nt][j] = 0.f;

        for (int kc = 0; kc < 32; kc++) {       // 32 chunks of 64 K-elements
            __syncthreads();                     // prev chunk's frag reads done
            // Load + convert f32 -> f16: 8 rows per thread per tile
#pragma unroll
            for (int i = 0; i < 8; i++) {
                const int row = row0 + 16 * i;
                float4 va = *reinterpret_cast<const float4*>(
                    Abase + (size_t)(16 * i) * D2H + kc * 64);
                float4 vb = *reinterpret_cast<const float4*>(
                    Bbase + (size_t)(16 * i) * D2H + kc * 64);
                *reinterpret_cast<uint2*>(&A_s[row * LDW + seg * 2]) =
                    make_uint2(f2h2(va.x, va.y), f2h2(va.z, va.w));
                *reinterpret_cast<uint2*>(&B_s[row * LDW + seg * 2]) =
                    make_uint2(f2h2(vb.x, vb.y), f2h2(vb.z, vb.w));
            }
            __syncthreads();

#pragma unroll
            for (int kk = 0; kk < 4; kk++) {     // 4 k-steps of K=16
                const int k0 = kk * 8;           // word offset (16 halves)
                uint32_t af[2][4];
#pragma unroll
                for (int mt = 0; mt < 2; mt++) {
                    const int rf = (wm * 32 + mt * 16 + gid) * LDW + k0 + tig;
                    af[mt][0] = A_s[rf];                 // row g,   k 2t..2t+1
                    af[mt][1] = A_s[rf + 8 * LDW];       // row g+8, k 2t..2t+1
                    af[mt][2] = A_s[rf + 4];             // row g,   k +8
                    af[mt][3] = A_s[rf + 8 * LDW + 4];   // row g+8, k +8
                }
                uint32_t bf[8][2];
#pragma unroll
                for (int nt = 0; nt < 8; nt++) {
                    const int c0 = (wn * 64 + nt * 8 + gid) * LDW + k0 + tig;
                    bf[nt][0] = B_s[c0];
                    bf[nt][1] = B_s[c0 + 4];
                }
#pragma unroll
                for (int mt = 0; mt < 2; mt++)
#pragma unroll
                    for (int nt = 0; nt < 8; nt++) {
                        asm volatile(
                            "mma.sync.aligned.m16n8k16.row.col.f32.f16.f16.f32 "
                            "{%0,%1,%2,%3}, {%4,%5,%6,%7}, {%8,%9}, {%0,%1,%2,%3};"
                            : "+f"(acc[mt][nt][0]), "+f"(acc[mt][nt][1]),
                              "+f"(acc[mt][nt][2]), "+f"(acc[mt][nt][3])
                            : "r"(af[mt][0]), "r"(af[mt][1]),
                              "r"(af[mt][2]), "r"(af[mt][3]),
                              "r"(bf[nt][0]), "r"(bf[nt][1]));
                    }
            }
        }

        // Epilogue: tanh(acc + wq) * V, accumulated per row
#pragma unroll
        for (int mt = 0; mt < 2; mt++)
#pragma unroll
            for (int nt = 0; nt < 8; nt++)
#pragma unroll
                for (int j = 0; j < 4; j++) {
                    const int nl = wn * 64 + nt * 8 + 2 * tig + (j & 1);
                    const float x = acc[mt][nt][j] + wq_s[nl];
                    const float e = __expf(2.f * x);
                    sp[mt][j >> 1] += (1.f - 2.f / (e + 1.f)) * V_s[nl];
                }
    }

    // Reduce partial scores: 4 lanes/group share a row; 2 N-warps share a row
#pragma unroll
    for (int mt = 0; mt < 2; mt++)
#pragma unroll
        for (int rh = 0; rh < 2; rh++) {
            float v = sp[mt][rh];
            v += __shfl_xor_sync(0xffffffffu, v, 1);
            v += __shfl_xor_sync(0xffffffffu, v, 2);
            if (tig == 0)
                atomicAdd(&scores_s[wm * 32 + mt * 16 + rh * 8 + gid], v);
        }
    __syncthreads();
    if (tid < 128)   // V_b omitted: softmax is shift-invariant
        g_scores[(size_t)b * SS + stile * 128 + tid] = scores_s[tid];
}

// ---------------------------------------------------------------------------
// Kernel C: softmax over S per batch
// ---------------------------------------------------------------------------
__global__ void softmax_kernel() {
    int b = blockIdx.x, tid = threadIdx.x;   // 256 threads
    __shared__ float red[256];
    float v[8];
    float mx = -1e30f;
#pragma unroll
    for (int i = 0; i < 8; i++) {
        v[i] = g_scores[b * SS + i * 256 + tid];
        mx = fmaxf(mx, v[i]);
    }
    red[tid] = mx;
    __syncthreads();
    for (int s = 128; s > 0; s >>= 1) {
        if (tid < s) red[tid] = fmaxf(red[tid], red[tid + s]);
        __syncthreads();
    }
    mx = red[0];
    __syncthreads();
    float sum = 0.f;
#pragma unroll
    for (int i = 0; i < 8; i++) {
        v[i] = __expf(v[i] - mx);
        sum += v[i];
    }
    red[tid] = sum;
    __syncthreads();
    for (int s = 128; s > 0; s >>= 1) {
        if (tid < s) red[tid] += red[tid + s];
        __syncthreads();
    }
    const float inv = 1.f / red[0];
#pragma unroll
    for (int i = 0; i < 8; i++)
        g_weights[b * SS + i * 256 + tid] = v[i] * inv;
}

// ---------------------------------------------------------------------------
// Kernel D1: partial context over an S-chunk (deterministic, no atomics)
// ---------------------------------------------------------------------------
__global__ void ctx_part_kernel(const float* __restrict__ enc) {
    int bb = blockIdx.x, sc = blockIdx.y, t = threadIdx.x;   // 512 threads
    __shared__ float w_s[256];
    if (t < 256) w_s[t] = g_weights[bb * SS + sc * 256 + t];
    __syncthreads();
    const float4* base =
        reinterpret_cast<const float4*>(enc + ((size_t)bb * SS + (size_t)sc * 256) * D2H);
    float4 acc = make_float4(0.f, 0.f, 0.f, 0.f);
#pragma unroll 4
    for (int s = 0; s < 256; s++) {
        float w = w_s[s];
        float4 e = base[(size_t)s * (D2H / 4) + t];
        acc.x += w * e.x; acc.y += w * e.y;
        acc.z += w * e.z; acc.w += w * e.w;
    }
    *reinterpret_cast<float4*>(g_part + ((size_t)sc * BB + bb) * D2H + t * 4) = acc;
}

// Kernel D2: sum the 8 S-chunk partials -> output [B, 1, 2H]
__global__ void ctx_reduce_kernel(float* __restrict__ out) {
    int i = blockIdx.x * blockDim.x + threadIdx.x;
    float s = 0.f;
#pragma unroll
    for (int sc = 0; sc < 8; sc++) s += g_part[sc * (BB * D2H) + i];
    out[i] = s;
}

// ---------------------------------------------------------------------------
extern "C" void kernel_launch(void* const* d_in, const int* in_sizes, int n_in,
                              void* d_out, int out_size) {
    const float* enc = (const float*)d_in[0];   // [32, 2048, 2048]
    const float* dh  = (const float*)d_in[1];   // [1, 32, 1024]
    const float* W_w = (const float*)d_in[2];   // [1024, 1024]
    const float* W_b = (const float*)d_in[3];   // [1024]
    const float* U_w = (const float*)d_in[4];   // [1024, 2048]
    const float* U_b = (const float*)d_in[5];   // [1024]
    const float* V_w = (const float*)d_in[6];   // [1, 1024]
    float* out = (float*)d_out;                 // [32, 1, 2048]

    wq_kernel<<<dim3(32, 8), 128>>>(dh, W_w, W_b, U_b);
    score_kernel<<<512, 256>>>(enc, U_w, V_w);
    softmax_kernel<<<32, 256>>>();
    ctx_part_kernel<<<dim3(32, 8), 512>>>(enc);
    ctx_reduce_kernel<<<128, 512>>>(out);
}

// round 14
// speedup vs baseline: 2.7182x; 1.2526x over previous
#include <cuda_runtime.h>
#include <cuda_fp16.h>
#include <cstdint>

#define BB 32
#define SS 2048
#define HH 1024
#define D2H 2048

// Scratch (device globals — no allocation allowed)
__device__ float g_wq[BB * HH];            // W(dh) + W_b + U_b
__device__ float g_spart[8 * BB * SS];     // per-N-chunk partial scores
__device__ float g_weights[BB * SS];
__device__ float g_part[8 * BB * D2H];

__device__ __forceinline__ uint32_t f2h2(float x, float y) {
    __half2 h = __floats2half2_rn(x, y);
    return *reinterpret_cast<uint32_t*>(&h);
}

// ---------------------------------------------------------------------------
// Kernel A: wq[b][k] = dh[b]·W_w[k] + W_b[k] + U_b[k]
// ---------------------------------------------------------------------------
__global__ void wq_kernel(const float* __restrict__ dh,
                          const float* __restrict__ W_w,
                          const float* __restrict__ W_b,
                          const float* __restrict__ U_b) {
    int b = blockIdx.x;
    int k = blockIdx.y * 128 + threadIdx.x;
    __shared__ float dh_s[HH];
    for (int i = threadIdx.x; i < HH; i += 128) dh_s[i] = dh[b * HH + i];
    __syncthreads();
    const float4* wrow = reinterpret_cast<const float4*>(W_w + (size_t)k * HH);
    const float4* dv   = reinterpret_cast<const float4*>(dh_s);
    float acc = 0.f;
#pragma unroll 8
    for (int i = 0; i < HH / 4; i++) {
        float4 w = wrow[i];
        float4 d = dv[i];
        acc += w.x * d.x + w.y * d.y + w.z * d.z + w.w * d.w;
    }
    g_wq[b * HH + k] = acc + W_b[k] + U_b[k];
}

// ---------------------------------------------------------------------------
// Kernel B: fused GEMM(enc @ U^T) + tanh + V-dot -> partial scores
// Grid 4096: nc = bx&7 (fastest -> the 8 N-chunk CTAs of one M-tile are
// co-resident and share the A tile through L2; full U_w stays L2-hot).
// CTA: 128 rows x 128 cols, fp16 mma.sync.m16n8k16, fp32 accum.
// 8 warps as 4(M) x 2(N); K-chunk = 64 elements; 2 CTAs/SM.
// ---------------------------------------------------------------------------
#define LDW 36   // smem row stride in 32-bit words (32 half2 + 4 pad)

__global__ __launch_bounds__(256, 2)
void score_kernel(const float* __restrict__ enc,
                  const float* __restrict__ Uw,
                  const float* __restrict__ Vw) {
    __shared__ uint32_t A_s[128 * LDW];   // enc tile  [m][k] as half2 words
    __shared__ uint32_t B_s[128 * LDW];   // U_w tile  [n][k] as half2 words
    __shared__ float wq_s[128];
    __shared__ float V_s[128];
    __shared__ float scores_s[128];

    const int tid  = threadIdx.x;
    const int lane = tid & 31;
    const int warp = tid >> 5;
    const int wm   = warp & 3;    // warp row (0..3) -> 32 rows each
    const int wn   = warp >> 2;   // warp col (0..1) -> 64 cols each
    const int gid  = lane >> 2;   // group id (0..7)
    const int tig  = lane & 3;    // thread-in-group

    const int nc    = blockIdx.x & 7;
    const int mtile = blockIdx.x >> 3;
    const int b     = mtile >> 4;
    const int stile = mtile & 15;

    // Loader coords: seg = 4-float segment (0..15), rows row0 + 16*i
    const int seg  = tid & 15;
    const int row0 = tid >> 4;    // 0..15
    const float* Abase =
        enc + ((size_t)(b * SS + stile * 128) + row0) * D2H + seg * 4;
    const float* Bbase =
        Uw + ((size_t)(nc * 128) + row0) * D2H + seg * 4;

    if (tid < 128) {
        scores_s[tid] = 0.f;
        wq_s[tid] = g_wq[b * HH + nc * 128 + tid];
        V_s[tid]  = Vw[nc * 128 + tid];
    }

    float acc[2][8][4];
#pragma unroll
    for (int mt = 0; mt < 2; mt++)
#pragma unroll
        for (int nt = 0; nt < 8; nt++)
#pragma unroll
            for (int j = 0; j < 4; j++) acc[mt][nt][j] = 0.f;

    for (int kc = 0; kc < 32; kc++) {       // 32 chunks of 64 K-elements
        __syncthreads();                     // prev chunk's frag reads done
        // Load + convert f32 -> f16: 8 rows per thread per tile
#pragma unroll
        for (int i = 0; i < 8; i++) {
            const int row = row0 + 16 * i;
            float4 va = *reinterpret_cast<const float4*>(
                Abase + (size_t)(16 * i) * D2H + kc * 64);
            float4 vb = *reinterpret_cast<const float4*>(
                Bbase + (size_t)(16 * i) * D2H + kc * 64);
            *reinterpret_cast<uint2*>(&A_s[row * LDW + seg * 2]) =
                make_uint2(f2h2(va.x, va.y), f2h2(va.z, va.w));
            *reinterpret_cast<uint2*>(&B_s[row * LDW + seg * 2]) =
                make_uint2(f2h2(vb.x, vb.y), f2h2(vb.z, vb.w));
        }
        __syncthreads();

#pragma unroll
        for (int kk = 0; kk < 4; kk++) {     // 4 k-steps of K=16
            const int k0 = kk * 8;           // word offset (16 halves)
            uint32_t af[2][4];
#pragma unroll
            for (int mt = 0; mt < 2; mt++) {
                const int rf = (wm * 32 + mt * 16 + gid) * LDW + k0 + tig;
                af[mt][0] = A_s[rf];                 // row g,   k 2t..2t+1
                af[mt][1] = A_s[rf + 8 * LDW];       // row g+8, k 2t..2t+1
                af[mt][2] = A_s[rf + 4];             // row g,   k +8
                af[mt][3] = A_s[rf + 8 * LDW + 4];   // row g+8, k +8
            }
            uint32_t bf[8][2];
#pragma unroll
            for (int nt = 0; nt < 8; nt++) {
                const int c0 = (wn * 64 + nt * 8 + gid) * LDW + k0 + tig;
                bf[nt][0] = B_s[c0];
                bf[nt][1] = B_s[c0 + 4];
            }
#pragma unroll
            for (int mt = 0; mt < 2; mt++)
#pragma unroll
                for (int nt = 0; nt < 8; nt++) {
                    asm volatile(
                        "mma.sync.aligned.m16n8k16.row.col.f32.f16.f16.f32 "
                        "{%0,%1,%2,%3}, {%4,%5,%6,%7}, {%8,%9}, {%0,%1,%2,%3};"
                        : "+f"(acc[mt][nt][0]), "+f"(acc[mt][nt][1]),
                          "+f"(acc[mt][nt][2]), "+f"(acc[mt][nt][3])
                        : "r"(af[mt][0]), "r"(af[mt][1]),
                          "r"(af[mt][2]), "r"(af[mt][3]),
                          "r"(bf[nt][0]), "r"(bf[nt][1]));
                }
        }
    }

    // Epilogue: tanh(acc + wq) * V, accumulated per row
    float sp[2][2] = {{0.f, 0.f}, {0.f, 0.f}};
#pragma unroll
    for (int mt = 0; mt < 2; mt++)
#pragma unroll
        for (int nt = 0; nt < 8; nt++)
#pragma unroll
            for (int j = 0; j < 4; j++) {
                const int nl = wn * 64 + nt * 8 + 2 * tig + (j & 1);
                const float x = acc[mt][nt][j] + wq_s[nl];
                const float e = __expf(2.f * x);
                sp[mt][j >> 1] += (1.f - 2.f / (e + 1.f)) * V_s[nl];
            }

    // Reduce partial scores: 4 lanes/group share a row; 2 N-warps share a row
#pragma unroll
    for (int mt = 0; mt < 2; mt++)
#pragma unroll
        for (int rh = 0; rh < 2; rh++) {
            float v = sp[mt][rh];
            v += __shfl_xor_sync(0xffffffffu, v, 1);
            v += __shfl_xor_sync(0xffffffffu, v, 2);
            if (tig == 0)
                atomicAdd(&scores_s[wm * 32 + mt * 16 + rh * 8 + gid], v);
        }
    __syncthreads();
    if (tid < 128)   // V_b omitted: softmax is shift-invariant
        g_spart[(size_t)nc * (BB * SS) + (size_t)b * SS + stile * 128 + tid] =
            scores_s[tid];
}

// ---------------------------------------------------------------------------
// Kernel C: sum 8 N-chunk partials, softmax over S per batch
// ---------------------------------------------------------------------------
__global__ void softmax_kernel() {
    int b = blockIdx.x, tid = threadIdx.x;   // 256 threads
    __shared__ float red[256];
    float v[8];
    float mx = -1e30f;
#pragma unroll
    for (int i = 0; i < 8; i++) {
        const int idx = b * SS + i * 256 + tid;
        float x = 0.f;
#pragma unroll
        for (int p = 0; p < 8; p++) x += g_spart[p * (BB * SS) + idx];
        v[i] = x;
        mx = fmaxf(mx, x);
    }
    red[tid] = mx;
    __syncthreads();
    for (int s = 128; s > 0; s >>= 1) {
        if (tid < s) red[tid] = fmaxf(red[tid], red[tid + s]);
        __syncthreads();
    }
    mx = red[0];
    __syncthreads();
    float sum = 0.f;
#pragma unroll
    for (int i = 0; i < 8; i++) {
        v[i] = __expf(v[i] - mx);
        sum += v[i];
    }
    red[tid] = sum;
    __syncthreads();
    for (int s = 128; s > 0; s >>= 1) {
        if (tid < s) red[tid] += red[tid + s];
        __syncthreads();
    }
    const float inv = 1.f / red[0];
#pragma unroll
    for (int i = 0; i < 8; i++)
        g_weights[b * SS + i * 256 + tid] = v[i] * inv;
}

// ---------------------------------------------------------------------------
// Kernel D1: partial context over an S-chunk (deterministic, no atomics)
// ---------------------------------------------------------------------------
__global__ void ctx_part_kernel(const float* __restrict__ enc) {
    int bb = blockIdx.x, sc = blockIdx.y, t = threadIdx.x;   // 512 threads
    __shared__ float w_s[256];
    if (t < 256) w_s[t] = g_weights[bb * SS + sc * 256 + t];
    __syncthreads();
    const float4* base =
        reinterpret_cast<const float4*>(enc + ((size_t)bb * SS + (size_t)sc * 256) * D2H);
    float4 acc = make_float4(0.f, 0.f, 0.f, 0.f);
#pragma unroll 4
    for (int s = 0; s < 256; s++) {
        float w = w_s[s];
        float4 e = base[(size_t)s * (D2H / 4) + t];
        acc.x += w * e.x; acc.y += w * e.y;
        acc.z += w * e.z; acc.w += w * e.w;
    }
    *reinterpret_cast<float4*>(g_part + ((size_t)sc * BB + bb) * D2H + t * 4) = acc;
}

// Kernel D2: sum the 8 S-chunk partials -> output [B, 1, 2H]
__global__ void ctx_reduce_kernel(float* __restrict__ out) {
    int i = blockIdx.x * blockDim.x + threadIdx.x;
    float s = 0.f;
#pragma unroll
    for (int sc = 0; sc < 8; sc++) s += g_part[sc * (BB * D2H) + i];
    out[i] = s;
}

// ---------------------------------------------------------------------------
extern "C" void kernel_launch(void* const* d_in, const int* in_sizes, int n_in,
                              void* d_out, int out_size) {
    const float* enc = (const float*)d_in[0];   // [32, 2048, 2048]
    const float* dh  = (const float*)d_in[1];   // [1, 32, 1024]
    const float* W_w = (const float*)d_in[2];   // [1024, 1024]
    const float* W_b = (const float*)d_in[3];   // [1024]
    const float* U_w = (const float*)d_in[4];   // [1024, 2048]
    const float* U_b = (const float*)d_in[5];   // [1024]
    const float* V_w = (const float*)d_in[6];   // [1, 1024]
    float* out = (float*)d_out;                 // [32, 1, 2048]

    wq_kernel<<<dim3(32, 8), 128>>>(dh, W_w, W_b, U_b);
    score_kernel<<<4096, 256>>>(enc, U_w, V_w);
    softmax_kernel<<<32, 256>>>();
    ctx_part_kernel<<<dim3(32, 8), 512>>>(enc);
    ctx_reduce_kernel<<<128, 512>>>(out);
}

// round 15
// speedup vs baseline: 2.8382x; 1.0441x over previous
#include <cuda_runtime.h>
#include <cuda_fp16.h>
#include <cstdint>

#define BB 32
#define SS 2048
#define HH 1024
#define D2H 2048

// Scratch (device globals — no allocation allowed)
__device__ float g_wq[BB * HH];            // W(dh) + W_b + U_b
__device__ float g_spart[8 * BB * SS];     // per-N-chunk partial scores
__device__ float g_weights[BB * SS];
__device__ float g_part[8 * BB * D2H];

__device__ __forceinline__ uint32_t f2h2(float x, float y) {
    __half2 h = __floats2half2_rn(x, y);
    return *reinterpret_cast<uint32_t*>(&h);
}
__device__ __forceinline__ uint32_t s2u(const void* p) {
    uint32_t a;
    asm("{ .reg .u64 t; cvta.to.shared.u64 t, %1; cvt.u32.u64 %0, t; }"
        : "=r"(a) : "l"(p));
    return a;
}
__device__ __forceinline__ void ldsm_x4(uint32_t& r0, uint32_t& r1,
                                        uint32_t& r2, uint32_t& r3,
                                        uint32_t addr) {
    asm volatile("ldmatrix.sync.aligned.m8n8.x4.shared.b16 {%0,%1,%2,%3}, [%4];"
                 : "=r"(r0), "=r"(r1), "=r"(r2), "=r"(r3) : "r"(addr));
}

// ---------------------------------------------------------------------------
// Kernel A: wq[b][k] = dh[b]·W_w[k] + W_b[k] + U_b[k]
// ---------------------------------------------------------------------------
__global__ void wq_kernel(const float* __restrict__ dh,
                          const float* __restrict__ W_w,
                          const float* __restrict__ W_b,
                          const float* __restrict__ U_b) {
    int b = blockIdx.x;
    int k = blockIdx.y * 128 + threadIdx.x;
    __shared__ float dh_s[HH];
    for (int i = threadIdx.x; i < HH; i += 128) dh_s[i] = dh[b * HH + i];
    __syncthreads();
    const float4* wrow = reinterpret_cast<const float4*>(W_w + (size_t)k * HH);
    const float4* dv   = reinterpret_cast<const float4*>(dh_s);
    float acc = 0.f;
#pragma unroll 8
    for (int i = 0; i < HH / 4; i++) {
        float4 w = wrow[i];
        float4 d = dv[i];
        acc += w.x * d.x + w.y * d.y + w.z * d.z + w.w * d.w;
    }
    g_wq[b * HH + k] = acc + W_b[k] + U_b[k];
}

// ---------------------------------------------------------------------------
// Kernel B: fused GEMM(enc @ U^T) + tanh + V-dot -> partial scores
// Grid 4096: nc = bx&7 fastest (8 N-chunk CTAs share the A tile via L2).
// CTA 128x128, fp16 mma.sync.m16n8k16 fp32-accum, ldmatrix fragment loads.
// 8 warps as 4(M) x 2(N); K-chunk = 64 elements; 2 CTAs/SM.
// ---------------------------------------------------------------------------
#define LDW 36   // smem row stride in 32-bit words (32 half2 + 4 pad)

__global__ __launch_bounds__(256, 2)
void score_kernel(const float* __restrict__ enc,
                  const float* __restrict__ Uw,
                  const float* __restrict__ Vw) {
    __shared__ uint32_t A_s[128 * LDW];   // enc tile  [m][k] as half2 words
    __shared__ uint32_t B_s[128 * LDW];   // U_w tile  [n][k] as half2 words
    __shared__ float wq_s[128];
    __shared__ float V_s[128];
    __shared__ float scores_s[128];

    const int tid  = threadIdx.x;
    const int lane = tid & 31;
    const int warp = tid >> 5;
    const int wm   = warp & 3;    // warp row (0..3) -> 32 rows each
    const int wn   = warp >> 2;   // warp col (0..1) -> 64 cols each
    const int gid  = lane >> 2;   // group id (0..7)
    const int tig  = lane & 3;    // thread-in-group

    const int nc    = blockIdx.x & 7;
    const int mtile = blockIdx.x >> 3;
    const int b     = mtile >> 4;
    const int stile = mtile & 15;

    // Loader coords: seg = 4-float segment (0..15), rows row0 + 16*i
    const int seg  = tid & 15;
    const int row0 = tid >> 4;    // 0..15
    const float* Abase =
        enc + ((size_t)(b * SS + stile * 128) + row0) * D2H + seg * 4;
    const float* Bbase =
        Uw + ((size_t)(nc * 128) + row0) * D2H + seg * 4;

    if (tid < 128) {
        scores_s[tid] = 0.f;
        wq_s[tid] = g_wq[b * HH + nc * 128 + tid];
        V_s[tid]  = Vw[nc * 128 + tid];
    }

    // ldmatrix per-lane base addresses (byte, shared space).
    // A x4: mat0 rows g(0..7)@k0, mat1 rows +8@k0, mat2 rows@k0+8h, mat3 +8@+8h
    const int   rowA  = wm * 32 + (lane & 7) + ((lane >> 3) & 1) * 8;
    const int   wA    = ((lane >> 4) & 1) * 4;
    const uint32_t aAddr0 = s2u(A_s) + (uint32_t)(rowA * LDW + wA) * 4u;
    // B x4 (per j): mat0 rows nt=2j@k0, mat1 same rows@k0+8h, mat2 nt=2j+1@k0,
    // mat3 nt=2j+1@+8h   (rows: lanes16-31 -> +8 n-rows; word: lanes 8-15/24-31 -> +4)
    const int   rowB  = wn * 64 + ((lane >> 4) & 1) * 8 + (lane & 7);
    const int   wB    = ((lane >> 3) & 1) * 4;
    const uint32_t bAddr0 = s2u(B_s) + (uint32_t)(rowB * LDW + wB) * 4u;

    float acc[2][8][4];
#pragma unroll
    for (int mt = 0; mt < 2; mt++)
#pragma unroll
        for (int nt = 0; nt < 8; nt++)
#pragma unroll
            for (int j = 0; j < 4; j++) acc[mt][nt][j] = 0.f;

    for (int kc = 0; kc < 32; kc++) {       // 32 chunks of 64 K-elements
        __syncthreads();                     // prev chunk's frag reads done
        // Load + convert f32 -> f16: 8 rows per thread per tile
#pragma unroll
        for (int i = 0; i < 8; i++) {
            const int row = row0 + 16 * i;
            float4 va = *reinterpret_cast<const float4*>(
                Abase + (size_t)(16 * i) * D2H + kc * 64);
            float4 vb = *reinterpret_cast<const float4*>(
                Bbase + (size_t)(16 * i) * D2H + kc * 64);
            *reinterpret_cast<uint2*>(&A_s[row * LDW + seg * 2]) =
                make_uint2(f2h2(va.x, va.y), f2h2(va.z, va.w));
            *reinterpret_cast<uint2*>(&B_s[row * LDW + seg * 2]) =
                make_uint2(f2h2(vb.x, vb.y), f2h2(vb.z, vb.w));
        }
        __syncthreads();

#pragma unroll
        for (int kk = 0; kk < 4; kk++) {     // 4 k-steps of K=16
            const uint32_t koff = (uint32_t)(kk * 8 * 4);   // 8 words
            uint32_t af[2][4];
            ldsm_x4(af[0][0], af[0][1], af[0][2], af[0][3], aAddr0 + koff);
            ldsm_x4(af[1][0], af[1][1], af[1][2], af[1][3],
                    aAddr0 + 16u * LDW * 4u + koff);
            uint32_t bf[8][2];
#pragma unroll
            for (int j = 0; j < 4; j++)
                ldsm_x4(bf[2 * j][0], bf[2 * j][1],
                        bf[2 * j + 1][0], bf[2 * j + 1][1],
                        bAddr0 + (uint32_t)(j * 16 * LDW * 4) + koff);
#pragma unroll
            for (int mt = 0; mt < 2; mt++)
#pragma unroll
                for (int nt = 0; nt < 8; nt++) {
                    asm volatile(
                        "mma.sync.aligned.m16n8k16.row.col.f32.f16.f16.f32 "
                        "{%0,%1,%2,%3}, {%4,%5,%6,%7}, {%8,%9}, {%0,%1,%2,%3};"
                        : "+f"(acc[mt][nt][0]), "+f"(acc[mt][nt][1]),
                          "+f"(acc[mt][nt][2]), "+f"(acc[mt][nt][3])
                        : "r"(af[mt][0]), "r"(af[mt][1]),
                          "r"(af[mt][2]), "r"(af[mt][3]),
                          "r"(bf[nt][0]), "r"(bf[nt][1]));
                }
        }
    }

    // Epilogue: tanh(acc + wq) * V, accumulated per row
    float sp[2][2] = {{0.f, 0.f}, {0.f, 0.f}};
#pragma unroll
    for (int mt = 0; mt < 2; mt++)
#pragma unroll
        for (int nt = 0; nt < 8; nt++)
#pragma unroll
            for (int j = 0; j < 4; j++) {
                const int nl = wn * 64 + nt * 8 + 2 * tig + (j & 1);
                const float x = acc[mt][nt][j] + wq_s[nl];
                const float e = __expf(2.f * x);
                sp[mt][j >> 1] += (1.f - 2.f / (e + 1.f)) * V_s[nl];
            }

    // Reduce partial scores: 4 lanes/group share a row; 2 N-warps share a row
#pragma unroll
    for (int mt = 0; mt < 2; mt++)
#pragma unroll
        for (int rh = 0; rh < 2; rh++) {
            float v = sp[mt][rh];
            v += __shfl_xor_sync(0xffffffffu, v, 1);
            v += __shfl_xor_sync(0xffffffffu, v, 2);
            if (tig == 0)
                atomicAdd(&scores_s[wm * 32 + mt * 16 + rh * 8 + gid], v);
        }
    __syncthreads();
    if (tid < 128)   // V_b omitted: softmax is shift-invariant
        g_spart[(size_t)nc * (BB * SS) + (size_t)b * SS + stile * 128 + tid] =
            scores_s[tid];
}

// ---------------------------------------------------------------------------
// Kernel C: sum 8 N-chunk partials, softmax over S per batch
// ---------------------------------------------------------------------------
__global__ void softmax_kernel() {
    int b = blockIdx.x, tid = threadIdx.x;   // 256 threads
    __shared__ float red[256];
    float v[8];
    float mx = -1e30f;
#pragma unroll
    for (int i = 0; i < 8; i++) {
        const int idx = b * SS + i * 256 + tid;
        float x = 0.f;
#pragma unroll
        for (int p = 0; p < 8; p++) x += g_spart[p * (BB * SS) + idx];
        v[i] = x;
        mx = fmaxf(mx, x);
    }
    red[tid] = mx;
    __syncthreads();
    for (int s = 128; s > 0; s >>= 1) {
        if (tid < s) red[tid] = fmaxf(red[tid], red[tid + s]);
        __syncthreads();
    }
    mx = red[0];
    __syncthreads();
    float sum = 0.f;
#pragma unroll
    for (int i = 0; i < 8; i++) {
        v[i] = __expf(v[i] - mx);
        sum += v[i];
    }
    red[tid] = sum;
    __syncthreads();
    for (int s = 128; s > 0; s >>= 1) {
        if (tid < s) red[tid] += red[tid + s];
        __syncthreads();
    }
    const float inv = 1.f / red[0];
#pragma unroll
    for (int i = 0; i < 8; i++)
        g_weights[b * SS + i * 256 + tid] = v[i] * inv;
}

// ---------------------------------------------------------------------------
// Kernel D1: partial context over an S-chunk (deterministic, no atomics)
// ---------------------------------------------------------------------------
__global__ void ctx_part_kernel(const float* __restrict__ enc) {
    int bb = blockIdx.x, sc = blockIdx.y, t = threadIdx.x;   // 512 threads
    __shared__ float w_s[256];
    if (t < 256) w_s[t] = g_weights[bb * SS + sc * 256 + t];
    __syncthreads();
    const float4* base =
        reinterpret_cast<const float4*>(enc + ((size_t)bb * SS + (size_t)sc * 256) * D2H);
    float4 acc = make_float4(0.f, 0.f, 0.f, 0.f);
#pragma unroll 4
    for (int s = 0; s < 256; s++) {
        float w = w_s[s];
        float4 e = base[(size_t)s * (D2H / 4) + t];
        acc.x += w * e.x; acc.y += w * e.y;
        acc.z += w * e.z; acc.w += w * e.w;
    }
    *reinterpret_cast<float4*>(g_part + ((size_t)sc * BB + bb) * D2H + t * 4) = acc;
}

// Kernel D2: sum the 8 S-chunk partials -> output [B, 1, 2H]
__global__ void ctx_reduce_kernel(float* __restrict__ out) {
    int i = blockIdx.x * blockDim.x + threadIdx.x;
    float s = 0.f;
#pragma unroll
    for (int sc = 0; sc < 8; sc++) s += g_part[sc * (BB * D2H) + i];
    out[i] = s;
}

// ---------------------------------------------------------------------------
extern "C" void kernel_launch(void* const* d_in, const int* in_sizes, int n_in,
                              void* d_out, int out_size) {
    const float* enc = (const float*)d_in[0];   // [32, 2048, 2048]
    const float* dh  = (const float*)d_in[1];   // [1, 32, 1024]
    const float* W_w = (const float*)d_in[2];   // [1024, 1024]
    const float* W_b = (const float*)d_in[3];   // [1024]
    const float* U_w = (const float*)d_in[4];   // [1024, 2048]
    const float* U_b = (const float*)d_in[5];   // [1024]
    const float* V_w = (const float*)d_in[6];   // [1, 1024]
    float* out = (float*)d_out;                 // [32, 1, 2048]

    wq_kernel<<<dim3(32, 8), 128>>>(dh, W_w, W_b, U_b);
    score_kernel<<<4096, 256>>>(enc, U_w, V_w);
    softmax_kernel<<<32, 256>>>();
    ctx_part_kernel<<<dim3(32, 8), 512>>>(enc);
    ctx_reduce_kernel<<<128, 512>>>(out);
}